// round 10
// baseline (speedup 1.0000x reference)
#include <cuda_runtime.h>
#include <cuda_fp16.h>
#include <math.h>
#include <stdint.h>

#define NTOK 4096
#define DIM  1024
#define HID  4096
#define NEXP 8
#define TOPK 2
#define NSLOT (NTOK * TOPK)
#define MAXMT 72

#define TM 128
#define TN 256
#define BK 32
#define THREADS 512

#define ASTRIDE 80            // 64B data + 16B pad
#define BSTRIDE 528           // 512B data + 16B pad
#define A_BLK (128 * ASTRIDE)            // 10240
#define B_BLK (32 * BSTRIDE)             // 16896
#define STAGE_B (A_BLK + B_BLK)          // 27136
#define NSTAGE 3
#define SMEM_BYTES (1024 + NSTAGE * STAGE_B)  // 82432 (opt-in; proven R6/R8)

// ---- static scratch ----
__device__ __align__(128) __half g_xf[(size_t)NTOK * DIM];
__device__ __align__(128) __half g_w1f[(size_t)NEXP * DIM * HID];
__device__ __align__(128) __half g_w2f[(size_t)NEXP * HID * DIM];
__device__ __align__(128) __half g_hf[(size_t)NSLOT * HID];
__device__ __align__(128) float g_y[(size_t)NSLOT * DIM];

__device__ int   g_list_tok[NSLOT];
__device__ float g_list_wgt[NSLOT];
__device__ int   g_slot_of[NTOK * TOPK];
__device__ int   g_counts[NEXP];
__device__ int   g_offsets[NEXP];
__device__ int   g_cursor[NEXP];
__device__ int   g_tok_e[NTOK * TOPK];
__device__ float g_tok_w[NTOK * TOPK];
__device__ int   g_tile_e[MAXMT];
__device__ int   g_tile_r0[MAXMT];
__device__ int   g_num_mtiles;

// ===================== helpers =====================
__device__ __forceinline__ uint32_t smem_to_u32(const void* p) {
    uint32_t a;
    asm("{ .reg .u64 t; cvta.to.shared.u64 t, %1; cvt.u32.u64 %0, t; }"
        : "=r"(a) : "l"(p));
    return a;
}
__device__ __forceinline__ void cpa16(uint32_t dst, const void* src) {
    asm volatile("cp.async.cg.shared.global [%0], [%1], 16;"
                 :: "r"(dst), "l"(src));
}
#define CPA_COMMIT() asm volatile("cp.async.commit_group;" ::: "memory")
#define CPA_WAIT1()  asm volatile("cp.async.wait_group 1;" ::: "memory")

__device__ __forceinline__ void ldsm_x4(uint32_t* r, uint32_t addr) {
    asm volatile("ldmatrix.sync.aligned.m8n8.x4.shared.b16 {%0,%1,%2,%3}, [%4];"
        : "=r"(r[0]), "=r"(r[1]), "=r"(r[2]), "=r"(r[3]) : "r"(addr));
}
__device__ __forceinline__ void ldsm_x4_t(uint32_t* r, uint32_t addr) {
    asm volatile("ldmatrix.sync.aligned.m8n8.x4.trans.shared.b16 {%0,%1,%2,%3}, [%4];"
        : "=r"(r[0]), "=r"(r[1]), "=r"(r[2]), "=r"(r[3]) : "r"(addr));
}
__device__ __forceinline__ void mma16816(float* c, const uint32_t* a,
                                         uint32_t b0, uint32_t b1) {
    asm volatile("mma.sync.aligned.m16n8k16.row.col.f32.f16.f16.f32 "
        "{%0,%1,%2,%3}, {%4,%5,%6,%7}, {%8,%9}, {%0,%1,%2,%3};"
        : "+f"(c[0]), "+f"(c[1]), "+f"(c[2]), "+f"(c[3])
        : "r"(a[0]), "r"(a[1]), "r"(a[2]), "r"(a[3]), "r"(b0), "r"(b1));
}
__device__ __forceinline__ void mma_block(float acc[2][8][4],
                                          const uint32_t* a, const uint32_t* b) {
#pragma unroll
    for (int nt = 0; nt < 8; nt++) {
        uint32_t b0 = b[(nt >> 1) * 4 + (nt & 1) * 2];
        uint32_t b1 = b[(nt >> 1) * 4 + (nt & 1) * 2 + 1];
        mma16816(acc[0][nt], a, b0, b1);
        mma16816(acc[1][nt], a + 4, b0, b1);
    }
}
__device__ __forceinline__ float gelu_exact(float v) {
    return 0.5f * v * (1.0f + erff(v * 0.70710678118654752f));
}

// ===================== small kernels =====================
__global__ void init_kernel() {
    int i = threadIdx.x;
    if (i < NEXP) { g_counts[i] = 0; g_cursor[i] = 0; }
}

__global__ void gate_kernel(const float* __restrict__ x,
                            const float* __restrict__ gw,
                            const float* __restrict__ gb) {
    int warp = (blockIdx.x * blockDim.x + threadIdx.x) >> 5;
    int lane = threadIdx.x & 31;
    if (warp >= NTOK) return;
    const float* xr = x + (size_t)warp * DIM;
    float acc[NEXP];
#pragma unroll
    for (int e = 0; e < NEXP; e++) acc[e] = 0.0f;
    for (int d = lane; d < DIM; d += 32) {
        float xv = xr[d];
        const float* g = gw + d * NEXP;
#pragma unroll
        for (int e = 0; e < NEXP; e++) acc[e] += xv * g[e];
    }
#pragma unroll
    for (int e = 0; e < NEXP; e++) {
#pragma unroll
        for (int o = 16; o > 0; o >>= 1)
            acc[e] += __shfl_xor_sync(0xffffffffu, acc[e], o);
    }
    if (lane == 0) {
        float l[NEXP], g[NEXP];
        float mx = -1e30f;
#pragma unroll
        for (int e = 0; e < NEXP; e++) { l[e] = acc[e] + gb[e]; mx = fmaxf(mx, l[e]); }
        float Z = 0.0f;
#pragma unroll
        for (int e = 0; e < NEXP; e++) { g[e] = expf(l[e] - mx); Z += g[e]; }
        int b1 = 0;
#pragma unroll
        for (int e = 1; e < NEXP; e++) if (g[e] > g[b1]) b1 = e;
        int b2 = -1;
#pragma unroll
        for (int e = 0; e < NEXP; e++) {
            if (e == b1) continue;
            if (b2 < 0 || g[e] > g[b2]) b2 = e;
        }
        float v1 = g[b1] / Z, v2 = g[b2] / Z;
        float s = v1 + v2 + 1e-9f;
        g_tok_e[warp * 2 + 0] = b1;  g_tok_w[warp * 2 + 0] = v1 / s;
        g_tok_e[warp * 2 + 1] = b2;  g_tok_w[warp * 2 + 1] = v2 / s;
        atomicAdd(&g_counts[b1], 1);
        atomicAdd(&g_counts[b2], 1);
    }
}

__global__ void prefix_kernel() {
    int s = 0, nt = 0;
    for (int e = 0; e < NEXP; e++) {
        g_offsets[e] = s;
        int c = g_counts[e];
        s += c;
        int t = (c + TM - 1) / TM;
        for (int i = 0; i < t; i++) { g_tile_e[nt] = e; g_tile_r0[nt] = i * TM; nt++; }
    }
    g_num_mtiles = nt;
}

__global__ void scatter_kernel() {
    int t = blockIdx.x * blockDim.x + threadIdx.x;
    if (t >= NTOK) return;
#pragma unroll
    for (int k = 0; k < TOPK; k++) {
        int e = g_tok_e[t * 2 + k];
        int pos = atomicAdd(&g_cursor[e], 1);
        int slot = g_offsets[e] + pos;
        g_list_tok[slot] = t;
        g_list_wgt[slot] = g_tok_w[t * 2 + k];
        g_slot_of[t * 2 + k] = slot;
    }
}

// fp32 -> single fp16 (dest selected device-side: 0=x, 1=w1, 2=w2)
__global__ void convf_kernel(const float* __restrict__ src, int which, size_t n4) {
    size_t i = (size_t)blockIdx.x * blockDim.x + threadIdx.x;
    if (i >= n4) return;
    __half* d = (which == 0) ? g_xf : (which == 1) ? g_w1f : g_w2f;
    float4 v = ((const float4*)src)[i];
    ((__half2*)d)[i * 2 + 0] = __halves2half2(__float2half(v.x), __float2half(v.y));
    ((__half2*)d)[i * 2 + 1] = __halves2half2(__float2half(v.z), __float2half(v.w));
}

// ===================== GEMM kernels: single fp16 term, 128x256 tile, 3-stage =====================

__global__ __launch_bounds__(THREADS, 1)
void gemm1_mma(const float* __restrict__ b1) {
    int tile = blockIdx.y;
    if (tile >= g_num_mtiles) return;
    int e = g_tile_e[tile], row0 = g_tile_r0[tile];
    int cnt = g_counts[e], off = g_offsets[e];
    int col0 = blockIdx.x * TN;
    extern __shared__ char sm[];
    uint32_t smb = smem_to_u32(sm);
    int tid = threadIdx.x, lane = tid & 31, wid = tid >> 5;
    int* s_row = (int*)sm;
    if (tid < TM) s_row[tid] = g_list_tok[off + min(row0 + tid, max(cnt - 1, 0))];
    __syncthreads();

    const __half* B = g_w1f + (size_t)e * DIM * HID;

    auto load_chunk = [&](int c) {
        int kk = c << 5;
        int slot = c % NSTAGE;
        uint32_t ab = smb + 1024 + slot * STAGE_B;
        uint32_t bb = ab + A_BLK;
        {   // A: 128 rows x 4 x 16B
            int r = tid >> 2, ch = tid & 3;
            size_t so = (size_t)s_row[r] * DIM + kk;
            cpa16(ab + r * ASTRIDE + ch * 16, (const char*)(g_xf + so) + ch * 16);
        }
#pragma unroll
        for (int it = 0; it < 2; it++) {  // B: 32 rows x 32 x 16B
            int item = tid + (it << 9);
            int r = item >> 5, ch = item & 31;
            size_t so = (size_t)(kk + r) * HID + col0;
            cpa16(bb + r * BSTRIDE + ch * 16, (const char*)(B + so) + ch * 16);
        }
    };

    float acc[2][8][4];
#pragma unroll
    for (int a = 0; a < 2; a++)
#pragma unroll
        for (int b = 0; b < 8; b++)
#pragma unroll
            for (int q = 0; q < 4; q++) acc[a][b][q] = 0.0f;

    int m0 = (wid >> 2) * 32;
    int n0w = (wid & 3) * 64;
    uint32_t aoff = (uint32_t)((m0 + (lane & 15)) * ASTRIDE + (lane >> 4) * 16);
    uint32_t boff = (uint32_t)(((((lane >> 3) & 1) << 3) + (lane & 7)) * BSTRIDE +
                               (n0w + (lane >> 4) * 8) * 2);

    load_chunk(0); CPA_COMMIT();
    load_chunk(1); CPA_COMMIT();
    const int NCH = DIM / BK;            // 32
    for (int c = 0; c < NCH; c++) {
        CPA_WAIT1();
        __syncthreads();
        // slot (c+2)%NSTAGE held chunk c-1; all threads finished computing
        // c-1 before this barrier, so overwriting now is safe.
        if (c + 2 < NCH) load_chunk(c + 2);
        CPA_COMMIT();
        uint32_t ab = smb + 1024 + (c % NSTAGE) * STAGE_B;
        uint32_t bb = ab + A_BLK;
#pragma unroll
        for (int ks = 0; ks < 2; ks++) {
            uint32_t a[8], b[16];
            uint32_t aa = ab + aoff + ks * 32;
            uint32_t ba = bb + boff + ks * 16 * BSTRIDE;
            ldsm_x4(a,     aa);
            ldsm_x4(a + 4, aa + 16 * ASTRIDE);
#pragma unroll
            for (int ng = 0; ng < 4; ng++) ldsm_x4_t(b + 4 * ng, ba + ng * 32);
            mma_block(acc, a, b);
        }
    }

    int qr = lane >> 2, qc = (lane & 3) * 2;
#pragma unroll
    for (int mt = 0; mt < 2; mt++) {
#pragma unroll
        for (int i = 0; i < 2; i++) {
            int ml = m0 + mt * 16 + qr + i * 8;
            int r = row0 + ml;
            if (r < cnt) {
                size_t sl2 = (size_t)(off + r);
#pragma unroll
                for (int nt = 0; nt < 8; nt++) {
                    int col = col0 + n0w + nt * 8 + qc;
                    float2 bv = *(const float2*)(b1 + (size_t)e * HID + col);
                    float g0 = gelu_exact(acc[mt][nt][i * 2 + 0] + bv.x);
                    float g1 = gelu_exact(acc[mt][nt][i * 2 + 1] + bv.y);
                    *(__half2*)(g_hf + sl2 * HID + col) =
                        __halves2half2(__float2half(g0), __float2half(g1));
                }
            }
        }
    }
}

__global__ __launch_bounds__(THREADS, 1)
void gemm2_mma(const float* __restrict__ b2) {
    int tile = blockIdx.y;
    if (tile >= g_num_mtiles) return;
    int e = g_tile_e[tile], row0 = g_tile_r0[tile];
    int cnt = g_counts[e], off = g_offsets[e];
    int col0 = blockIdx.x * TN;
    extern __shared__ char sm[];
    uint32_t smb = smem_to_u32(sm);
    int tid = threadIdx.x, lane = tid & 31, wid = tid >> 5;
    int* s_row = (int*)sm;
    float* s_wgt = (float*)(sm + 512);
    if (tid < TM) {
        int sl = off + min(row0 + tid, max(cnt - 1, 0));
        s_row[tid] = sl;
        s_wgt[tid] = g_list_wgt[sl];
    }
    __syncthreads();

    const __half* B = g_w2f + (size_t)e * HID * DIM;

    auto load_chunk = [&](int c) {
        int kk = c << 5;
        int slot = c % NSTAGE;
        uint32_t ab = smb + 1024 + slot * STAGE_B;
        uint32_t bb = ab + A_BLK;
        {
            int r = tid >> 2, ch = tid & 3;
            size_t so = (size_t)s_row[r] * HID + kk;
            cpa16(ab + r * ASTRIDE + ch * 16, (const char*)(g_hf + so) + ch * 16);
        }
#pragma unroll
        for (int it = 0; it < 2; it++) {
            int item = tid + (it << 9);
            int r = item >> 5, ch = item & 31;
            size_t so = (size_t)(kk + r) * DIM + col0;
            cpa16(bb + r * BSTRIDE + ch * 16, (const char*)(B + so) + ch * 16);
        }
    };

    float acc[2][8][4];
#pragma unroll
    for (int a = 0; a < 2; a++)
#pragma unroll
        for (int b = 0; b < 8; b++)
#pragma unroll
            for (int q = 0; q < 4; q++) acc[a][b][q] = 0.0f;

    int m0 = (wid >> 2) * 32;
    int n0w = (wid & 3) * 64;
    uint32_t aoff = (uint32_t)((m0 + (lane & 15)) * ASTRIDE + (lane >> 4) * 16);
    uint32_t boff = (uint32_t)(((((lane >> 3) & 1) << 3) + (lane & 7)) * BSTRIDE +
                               (n0w + (lane >> 4) * 8) * 2);

    load_chunk(0); CPA_COMMIT();
    load_chunk(1); CPA_COMMIT();
    const int NCH = HID / BK;            // 128
    for (int c = 0; c < NCH; c++) {
        CPA_WAIT1();
        __syncthreads();
        if (c + 2 < NCH) load_chunk(c + 2);
        CPA_COMMIT();
        uint32_t ab = smb + 1024 + (c % NSTAGE) * STAGE_B;
        uint32_t bb = ab + A_BLK;
#pragma unroll
        for (int ks = 0; ks < 2; ks++) {
            uint32_t a[8], b[16];
            uint32_t aa = ab + aoff + ks * 32;
            uint32_t ba = bb + boff + ks * 16 * BSTRIDE;
            ldsm_x4(a,     aa);
            ldsm_x4(a + 4, aa + 16 * ASTRIDE);
#pragma unroll
            for (int ng = 0; ng < 4; ng++) ldsm_x4_t(b + 4 * ng, ba + ng * 32);
            mma_block(acc, a, b);
        }
    }

    int qr = lane >> 2, qc = (lane & 3) * 2;
#pragma unroll
    for (int mt = 0; mt < 2; mt++) {
#pragma unroll
        for (int i = 0; i < 2; i++) {
            int ml = m0 + mt * 16 + qr + i * 8;
            int r = row0 + ml;
            if (r < cnt) {
                size_t sl2 = (size_t)(off + r);
                float wgt = s_wgt[ml];
#pragma unroll
                for (int nt = 0; nt < 8; nt++) {
                    int col = col0 + n0w + nt * 8 + qc;
                    float2 bv = *(const float2*)(b2 + (size_t)e * DIM + col);
                    float y0 = wgt * (acc[mt][nt][i * 2 + 0] + bv.x);
                    float y1 = wgt * (acc[mt][nt][i * 2 + 1] + bv.y);
                    *(float2*)(g_y + sl2 * DIM + col) = make_float2(y0, y1);
                }
            }
        }
    }
}

// ===================== combine =====================
__global__ void combine_kernel(float* __restrict__ out) {
    int i = blockIdx.x * blockDim.x + threadIdx.x;
    if (i >= NTOK * DIM / 4) return;
    int t = i / (DIM / 4);
    int d4 = i % (DIM / 4);
    int s0 = g_slot_of[t * 2 + 0];
    int s1 = g_slot_of[t * 2 + 1];
    float4 a = ((const float4*)(g_y + (size_t)s0 * DIM))[d4];
    float4 b = ((const float4*)(g_y + (size_t)s1 * DIM))[d4];
    float4 o;
    o.x = a.x + b.x; o.y = a.y + b.y; o.z = a.z + b.z; o.w = a.w + b.w;
    ((float4*)out)[i] = o;
}

// ===================== launch =====================
extern "C" void kernel_launch(void* const* d_in, const int* in_sizes, int n_in,
                              void* d_out, int out_size) {
    const float* x  = (const float*)d_in[0];
    const float* gw = (const float*)d_in[1];
    const float* gb = (const float*)d_in[2];
    const float* w1 = (const float*)d_in[3];
    const float* b1 = (const float*)d_in[4];
    const float* w2 = (const float*)d_in[5];
    const float* b2 = (const float*)d_in[6];
    float* out = (float*)d_out;

    cudaFuncSetAttribute(gemm1_mma, cudaFuncAttributeMaxDynamicSharedMemorySize, SMEM_BYTES);
    cudaFuncSetAttribute(gemm2_mma, cudaFuncAttributeMaxDynamicSharedMemorySize, SMEM_BYTES);

    init_kernel<<<1, 32>>>();
    gate_kernel<<<NTOK / 8, 256>>>(x, gw, gb);
    prefix_kernel<<<1, 1>>>();
    scatter_kernel<<<NTOK / 256, 256>>>();

    size_t n4x = (size_t)NTOK * DIM / 4;
    size_t n4w = (size_t)NEXP * DIM * HID / 4;
    convf_kernel<<<(unsigned)((n4x + 255) / 256), 256>>>(x,  0, n4x);
    convf_kernel<<<(unsigned)((n4w + 255) / 256), 256>>>(w1, 1, n4w);
    convf_kernel<<<(unsigned)((n4w + 255) / 256), 256>>>(w2, 2, n4w);

    gemm1_mma<<<dim3(HID / TN, MAXMT), THREADS, SMEM_BYTES>>>(b1);
    gemm2_mma<<<dim3(DIM / TN, MAXMT), THREADS, SMEM_BYTES>>>(b2);
    combine_kernel<<<(NTOK * DIM / 4 + 255) / 256, 256>>>(out);
}